// round 1
// baseline (speedup 1.0000x reference)
#include <cuda_runtime.h>

// ---------------- problem constants ----------------
#define NV 16384
#define NC 8192
#define NE 65536
#define BB 1024
#define B4 256            // BB / 4 floats per float4 lane
#define CLIPV 15.0f
#define EPSF 1e-6f
// ABS_MIN = -log(tanh(15/2)) = 2*e^-15 (to f32)
#define ABS_MIN 6.1180464e-07f

// ---------------- scratch (static device globals: allocation-free) ----------
__device__ float g_colsum [(size_t)NV * BB];   // 64 MB: col_sum(We*msg_C2V)
__device__ float g_colsum2[(size_t)NV * BB];   // 64 MB: col_sum(We*msg_C2V_new)
__device__ float g_amp    [(size_t)NC * BB];   // 32 MB: row_sum(log tanh)
__device__ float g_cnt    [(size_t)NC * BB];   // 32 MB: row_sum(neg)

// log(tanh(x/2)) computed stably: t = expm1(-x)  =>  = log(-t) - log(2 + t)
__device__ __forceinline__ float logtanh_half(float al) {
    float t = expm1f(-al);          // in (-1, 0)
    return __logf(-t) - __logf(2.0f + t);
}

// ---------------- pass 1: colsum of We*msg_C2V ----------------
__global__ void __launch_bounds__(256) kColsum(
    const float4* __restrict__ mc2v, const int* __restrict__ var_idx,
    const float* __restrict__ We_p)
{
    int e = blockIdx.x;
    int t = threadIdx.x;
    int v = __ldg(var_idx + e);
    float We = __ldg(We_p);
    float4 m = __ldg(mc2v + (size_t)e * B4 + t);
    float* dst = g_colsum + (size_t)v * BB + t * 4;
    atomicAdd(dst + 0, We * m.x);
    atomicAdd(dst + 1, We * m.y);
    atomicAdd(dst + 2, We * m.z);
    atomicAdd(dst + 3, We * m.w);
}

// ---------------- pass 2: V-step + H-step accumulation ----------------
__global__ void __launch_bounds__(256) kV(
    const float4* __restrict__ chn, const float4* __restrict__ mc2v,
    const float4* __restrict__ mv2c,
    const int* __restrict__ var_idx, const int* __restrict__ chk_idx,
    const float* __restrict__ Wi_p, const float* __restrict__ We_p,
    const float* __restrict__ gm_p,
    float4* __restrict__ outV2C)
{
    int e = blockIdx.x;
    int t = threadIdx.x;
    int v = __ldg(var_idx + e);
    int c = __ldg(chk_idx + e);
    float Wi = __ldg(Wi_p), We = __ldg(We_p), g = __ldg(gm_p);

    float4 mc = __ldg(mc2v + (size_t)e * B4 + t);
    float4 mv = __ldg(mv2c + (size_t)e * B4 + t);
    float4 ch = __ldg(chn  + (size_t)v * B4 + t);
    const float4* cs4 = reinterpret_cast<const float4*>(g_colsum);
    float4 cs = cs4[(size_t)v * B4 + t];

    float mcs[4] = {mc.x, mc.y, mc.z, mc.w};
    float mvs[4] = {mv.x, mv.y, mv.z, mv.w};
    float chs[4] = {ch.x, ch.y, ch.z, ch.w};
    float css[4] = {cs.x, cs.y, cs.z, cs.w};
    float os[4], amp[4], neg[4];

    #pragma unroll
    for (int i = 0; i < 4; i++) {
        float lamw = We * mcs[i];
        float vnew = Wi * chs[i] + (css[i] - lamw);        // ell_w[v] + col_sum_loo
        float m2   = (1.0f - g) * mvs[i] + g * vnew;       // damped msg_V2C'
        os[i] = m2;
        float lam = fminf(fmaxf(m2, -CLIPV), CLIPV);
        neg[i] = (lam < 0.0f) ? 1.0f : 0.0f;
        float al = fminf(fmaxf(fabsf(lam), ABS_MIN), CLIPV);
        amp[i] = logtanh_half(al);
    }

    outV2C[(size_t)e * B4 + t] = make_float4(os[0], os[1], os[2], os[3]);

    float* ap = g_amp + (size_t)c * BB + t * 4;
    float* cp = g_cnt + (size_t)c * BB + t * 4;
    #pragma unroll
    for (int i = 0; i < 4; i++) {
        atomicAdd(ap + i, amp[i]);
        atomicAdd(cp + i, neg[i]);
    }
}

// ---------------- pass 3: H-step + colsum2 accumulation ----------------
__global__ void __launch_bounds__(256) kH(
    const float4* __restrict__ mc2v, const float4* __restrict__ v2cNew,
    const int* __restrict__ var_idx, const int* __restrict__ chk_idx,
    const float* __restrict__ We_p, const float* __restrict__ gm_p,
    float4* __restrict__ outC2V)
{
    int e = blockIdx.x;
    int t = threadIdx.x;
    int v = __ldg(var_idx + e);
    int c = __ldg(chk_idx + e);
    float We = __ldg(We_p), g = __ldg(gm_p);

    float4 m2v = __ldg(v2cNew + (size_t)e * B4 + t);
    float4 mc  = __ldg(mc2v   + (size_t)e * B4 + t);
    const float4* a4 = reinterpret_cast<const float4*>(g_amp);
    const float4* n4 = reinterpret_cast<const float4*>(g_cnt);
    float4 at = a4[(size_t)c * B4 + t];
    float4 nt = n4[(size_t)c * B4 + t];

    float m2s[4] = {m2v.x, m2v.y, m2v.z, m2v.w};
    float mcs[4] = {mc.x, mc.y, mc.z, mc.w};
    float ats[4] = {at.x, at.y, at.z, at.w};
    float nts[4] = {nt.x, nt.y, nt.z, nt.w};
    float os[4];

    #pragma unroll
    for (int i = 0; i < 4; i++) {
        float lam = fminf(fmaxf(m2s[i], -CLIPV), CLIPV);
        float ng  = (lam < 0.0f) ? 1.0f : 0.0f;
        float al  = fminf(fmaxf(fabsf(lam), ABS_MIN), CLIPV);
        float lt  = logtanh_half(al);
        float amp = fminf(ats[i] - lt, 0.0f);              // LOO; clamp <= 0 (pole guard)
        float cnt = nts[i] - ng;                           // LOO (exact small int)
        float sgn = 1.0f - 2.0f * fmodf(cnt, 2.0f);
        float y   = expf(amp) * (1.0f - EPSF);
        float h   = sgn * logf((1.0f + y) / (1.0f - y));   // sgn * 2 * atanh(y)
        os[i] = (1.0f - g) * mcs[i] + g * h;               // damped msg_C2V'
    }

    outC2V[(size_t)e * B4 + t] = make_float4(os[0], os[1], os[2], os[3]);

    float* dst = g_colsum2 + (size_t)v * BB + t * 4;
    #pragma unroll
    for (int i = 0; i < 4; i++)
        atomicAdd(dst + i, We * os[i]);
}

// ---------------- pass 4: marginals ----------------
__global__ void __launch_bounds__(256) kM(
    const float4* __restrict__ chn, const float* __restrict__ Wi_p,
    float4* __restrict__ outM)
{
    int n = blockIdx.x;
    int t = threadIdx.x;
    float Wi = __ldg(Wi_p);
    float4 ch = __ldg(chn + (size_t)n * B4 + t);
    const float4* cs4 = reinterpret_cast<const float4*>(g_colsum2);
    float4 cs = cs4[(size_t)n * B4 + t];
    outM[(size_t)n * B4 + t] =
        make_float4(Wi * ch.x + cs.x, Wi * ch.y + cs.y,
                    Wi * ch.z + cs.z, Wi * ch.w + cs.w);
}

// ---------------- launch ----------------
extern "C" void kernel_launch(void* const* d_in, const int* in_sizes, int n_in,
                              void* d_out, int out_size)
{
    (void)in_sizes; (void)n_in; (void)out_size;

    const float* chn  = (const float*)d_in[0];
    const float* mc2v = (const float*)d_in[1];
    const float* mv2c = (const float*)d_in[2];
    const float* Wi   = (const float*)d_in[3];
    const float* We   = (const float*)d_in[4];
    const float* gm   = (const float*)d_in[5];
    const int*   vi   = (const int*)d_in[6];
    const int*   ci   = (const int*)d_in[7];

    // outputs in reference return order: (msg_C2V, msg_V2C, output)
    float* outC2V = (float*)d_out;
    float* outV2C = outC2V + (size_t)NE * BB;
    float* outM   = outV2C + (size_t)NE * BB;

    void *pcs, *pcs2, *pamp, *pcnt;
    cudaGetSymbolAddress(&pcs,  g_colsum);
    cudaGetSymbolAddress(&pcs2, g_colsum2);
    cudaGetSymbolAddress(&pamp, g_amp);
    cudaGetSymbolAddress(&pcnt, g_cnt);

    cudaMemsetAsync(pcs,  0, sizeof(float) * (size_t)NV * BB, 0);
    cudaMemsetAsync(pcs2, 0, sizeof(float) * (size_t)NV * BB, 0);
    cudaMemsetAsync(pamp, 0, sizeof(float) * (size_t)NC * BB, 0);
    cudaMemsetAsync(pcnt, 0, sizeof(float) * (size_t)NC * BB, 0);

    kColsum<<<NE, 256>>>((const float4*)mc2v, vi, We);
    kV<<<NE, 256>>>((const float4*)chn, (const float4*)mc2v, (const float4*)mv2c,
                    vi, ci, Wi, We, gm, (float4*)outV2C);
    kH<<<NE, 256>>>((const float4*)mc2v, (const float4*)outV2C, vi, ci, We, gm,
                    (float4*)outC2V);
    kM<<<NV, 256>>>((const float4*)chn, Wi, (float4*)outM);
}

// round 2
// speedup vs baseline: 1.6772x; 1.6772x over previous
#include <cuda_runtime.h>

// ---------------- problem constants ----------------
#define NV 16384
#define NC 8192
#define NE 65536
#define BB 1024
#define B4 256            // BB/4 float4 per row
#define CLIPV 15.0f
#define EPSF 1e-6f
#define ABS_MIN 6.1180464e-07f   // -log(tanh(15/2))

#define DV_SMEM 16        // smem-cached edges per variable block
#define DC_SMEM 16        // smem-cached edges per check block

// ---------------- scratch (static device globals) ----------------
__device__ float g_colsum2[(size_t)NV * BB];   // 64 MB: col_sum(We*msg_C2V_new)
__device__ int g_cntV[NV];
__device__ int g_cntC[NC];
__device__ int g_rowV[NV + 1];
__device__ int g_rowC[NC + 1];
__device__ int g_curV[NV];
__device__ int g_curC[NC];
__device__ int g_edgeV[NE];
__device__ int g_edgeC[NE];

// log(tanh(x/2)) stable: t = expm1(-x) => log(-t) - log(2+t)
__device__ __forceinline__ float logtanh_half(float al) {
    float t = expm1f(-al);
    return __logf(-t) - __logf(2.0f + t);
}

__device__ __forceinline__ void red_add_v4(float* p, float4 v) {
    asm volatile("red.global.add.v4.f32 [%0], {%1, %2, %3, %4};"
                 :: "l"(p), "f"(v.x), "f"(v.y), "f"(v.z), "f"(v.w) : "memory");
}

// ---------------- CSR build ----------------
__global__ void __launch_bounds__(256) kCount(const int* __restrict__ vi,
                                              const int* __restrict__ ci)
{
    int e = blockIdx.x * 256 + threadIdx.x;
    if (e < NE) {
        atomicAdd(&g_cntV[__ldg(vi + e)], 1);
        atomicAdd(&g_cntC[__ldg(ci + e)], 1);
    }
}

__global__ void __launch_bounds__(1024) kScan()
{
    const bool isV = (blockIdx.x == 0);
    const int N = isV ? NV : NC;
    int* cnt = isV ? g_cntV : g_cntC;
    int* row = isV ? g_rowV : g_rowC;
    int* cur = isV ? g_curV : g_curC;
    const int CH = N / 1024;
    int t = threadIdx.x;
    int base = t * CH;
    int local[16];
    int s = 0;
    for (int i = 0; i < CH; i++) { local[i] = s; s += cnt[base + i]; }
    __shared__ int sm[1024];
    sm[t] = s;
    __syncthreads();
    for (int d = 1; d < 1024; d <<= 1) {
        int x = (t >= d) ? sm[t - d] : 0;
        __syncthreads();
        sm[t] += x;
        __syncthreads();
    }
    int excl = (t == 0) ? 0 : sm[t - 1];
    for (int i = 0; i < CH; i++) {
        row[base + i] = excl + local[i];
        cur[base + i] = excl + local[i];
    }
    if (t == 1023) row[N] = sm[1023];
}

__global__ void __launch_bounds__(256) kFill(const int* __restrict__ vi,
                                             const int* __restrict__ ci)
{
    int e = blockIdx.x * 256 + threadIdx.x;
    if (e < NE) {
        int p = atomicAdd(&g_curV[__ldg(vi + e)], 1);
        g_edgeV[p] = e;
        int q = atomicAdd(&g_curC[__ldg(ci + e)], 1);
        g_edgeC[q] = e;
    }
}

// ---------------- V step: variable-centric ----------------
// block = (variable, half-batch); 128 threads = 128 float4 columns
__global__ void __launch_bounds__(128) kV(
    const float4* __restrict__ chn, const float4* __restrict__ mc2v,
    const float4* __restrict__ mv2c,
    const float* __restrict__ Wi_p, const float* __restrict__ We_p,
    const float* __restrict__ gm_p,
    float4* __restrict__ outV2C)
{
    int v = blockIdx.x;
    int col = blockIdx.y * 128 + threadIdx.x;   // float4 column, row stride B4
    int s = g_rowV[v], e1 = g_rowV[v + 1];
    int deg = e1 - s;
    if (deg == 0) return;

    __shared__ float4 smc[DV_SMEM][128];

    float Wi = __ldg(Wi_p), We = __ldg(We_p), g = __ldg(gm_p);
    float4 ch = __ldg(chn + (size_t)v * B4 + col);

    float sx = 0.f, sy = 0.f, sz = 0.f, sw = 0.f;
    for (int j = 0; j < deg; j++) {
        int e = __ldg(&g_edgeV[s + j]);
        float4 m = __ldg(mc2v + (size_t)e * B4 + col);
        if (j < DV_SMEM) smc[j][threadIdx.x] = m;
        sx += m.x; sy += m.y; sz += m.z; sw += m.w;
    }

    float ellx = Wi * ch.x, elly = Wi * ch.y, ellz = Wi * ch.z, ellw = Wi * ch.w;
    float omg = 1.0f - g;

    for (int j = 0; j < deg; j++) {
        int e = __ldg(&g_edgeV[s + j]);
        float4 m = (j < DV_SMEM) ? smc[j][threadIdx.x]
                                 : __ldg(mc2v + (size_t)e * B4 + col);
        float4 mv = __ldg(mv2c + (size_t)e * B4 + col);
        float4 o;
        o.x = omg * mv.x + g * (ellx + We * (sx - m.x));
        o.y = omg * mv.y + g * (elly + We * (sy - m.y));
        o.z = omg * mv.z + g * (ellz + We * (sz - m.z));
        o.w = omg * mv.w + g * (ellw + We * (sw - m.w));
        outV2C[(size_t)e * B4 + col] = o;
    }
}

// ---------------- H step: check-centric ----------------
// block = (check, half-batch); 128 threads
__global__ void __launch_bounds__(128) kH(
    const float4* __restrict__ v2cNew, const float4* __restrict__ mc2v,
    const int* __restrict__ vi,
    const float* __restrict__ We_p, const float* __restrict__ gm_p,
    float4* __restrict__ outC2V)
{
    int c = blockIdx.x;
    int col = blockIdx.y * 128 + threadIdx.x;
    int s = g_rowC[c], e1 = g_rowC[c + 1];
    int deg = e1 - s;
    if (deg == 0) return;

    __shared__ float4 senc[DC_SMEM][128];

    float We = __ldg(We_p), g = __ldg(gm_p);
    float omg = 1.0f - g;

    float Slt[4] = {0.f, 0.f, 0.f, 0.f};
    int   Sng[4] = {0, 0, 0, 0};

    for (int j = 0; j < deg; j++) {
        int e = __ldg(&g_edgeC[s + j]);
        float4 l4 = __ldg(v2cNew + (size_t)e * B4 + col);
        float lam[4] = {l4.x, l4.y, l4.z, l4.w};
        float enc[4];
        #pragma unroll
        for (int i = 0; i < 4; i++) {
            float lm = fminf(fmaxf(lam[i], -CLIPV), CLIPV);
            int ng = (lm < 0.f) ? 1 : 0;
            float al = fminf(fmaxf(fabsf(lm), ABS_MIN), CLIPV);
            float lt = logtanh_half(al);           // lt < 0 always
            Slt[i] += lt;
            Sng[i] += ng;
            enc[i] = ng ? -lt : lt;                // sign encodes ng
        }
        if (j < DC_SMEM)
            senc[j][threadIdx.x] = make_float4(enc[0], enc[1], enc[2], enc[3]);
    }

    for (int j = 0; j < deg; j++) {
        int e = __ldg(&g_edgeC[s + j]);
        int v = __ldg(vi + e);
        float enc[4];
        if (j < DC_SMEM) {
            float4 e4 = senc[j][threadIdx.x];
            enc[0] = e4.x; enc[1] = e4.y; enc[2] = e4.z; enc[3] = e4.w;
        } else {
            float4 l4 = __ldg(v2cNew + (size_t)e * B4 + col);  // L2 hit
            float lam[4] = {l4.x, l4.y, l4.z, l4.w};
            #pragma unroll
            for (int i = 0; i < 4; i++) {
                float lm = fminf(fmaxf(lam[i], -CLIPV), CLIPV);
                int ng = (lm < 0.f) ? 1 : 0;
                float al = fminf(fmaxf(fabsf(lm), ABS_MIN), CLIPV);
                float lt = logtanh_half(al);
                enc[i] = ng ? -lt : lt;
            }
        }

        float4 mc = __ldg(mc2v + (size_t)e * B4 + col);
        float mcs[4] = {mc.x, mc.y, mc.z, mc.w};
        float os[4];
        #pragma unroll
        for (int i = 0; i < 4; i++) {
            int ng = (enc[i] > 0.f) ? 1 : 0;
            float lt = -fabsf(enc[i]);
            float amp = fminf(Slt[i] - lt, 0.0f);
            int cnt = Sng[i] - ng;
            float sgn = (cnt & 1) ? -1.0f : 1.0f;
            float y = __expf(amp) * (1.0f - EPSF);
            float h = sgn * __logf(__fdividef(1.0f + y, 1.0f - y));
            os[i] = omg * mcs[i] + g * h;
        }
        float4 o = make_float4(os[0], os[1], os[2], os[3]);
        outC2V[(size_t)e * B4 + col] = o;

        float* dst = g_colsum2 + (size_t)v * BB + col * 4;
        red_add_v4(dst, make_float4(We * o.x, We * o.y, We * o.z, We * o.w));
    }
}

// ---------------- M step: marginals ----------------
__global__ void __launch_bounds__(256) kM(
    const float4* __restrict__ chn, const float* __restrict__ Wi_p,
    float4* __restrict__ outM)
{
    int n = blockIdx.x;
    int t = threadIdx.x;
    float Wi = __ldg(Wi_p);
    float4 ch = __ldg(chn + (size_t)n * B4 + t);
    const float4* cs4 = reinterpret_cast<const float4*>(g_colsum2);
    float4 cs = cs4[(size_t)n * B4 + t];
    outM[(size_t)n * B4 + t] =
        make_float4(Wi * ch.x + cs.x, Wi * ch.y + cs.y,
                    Wi * ch.z + cs.z, Wi * ch.w + cs.w);
}

// ---------------- launch ----------------
extern "C" void kernel_launch(void* const* d_in, const int* in_sizes, int n_in,
                              void* d_out, int out_size)
{
    (void)in_sizes; (void)n_in; (void)out_size;

    const float* chn  = (const float*)d_in[0];
    const float* mc2v = (const float*)d_in[1];
    const float* mv2c = (const float*)d_in[2];
    const float* Wi   = (const float*)d_in[3];
    const float* We   = (const float*)d_in[4];
    const float* gm   = (const float*)d_in[5];
    const int*   vi   = (const int*)d_in[6];
    const int*   ci   = (const int*)d_in[7];

    // outputs: (msg_C2V, msg_V2C, output)
    float* outC2V = (float*)d_out;
    float* outV2C = outC2V + (size_t)NE * BB;
    float* outM   = outV2C + (size_t)NE * BB;

    void *pcs2, *pcv, *pcc;
    cudaGetSymbolAddress(&pcs2, g_colsum2);
    cudaGetSymbolAddress(&pcv, g_cntV);
    cudaGetSymbolAddress(&pcc, g_cntC);

    cudaMemsetAsync(pcs2, 0, sizeof(float) * (size_t)NV * BB, 0);
    cudaMemsetAsync(pcv, 0, sizeof(int) * NV, 0);
    cudaMemsetAsync(pcc, 0, sizeof(int) * NC, 0);

    kCount<<<NE / 256, 256>>>(vi, ci);
    kScan<<<2, 1024>>>();
    kFill<<<NE / 256, 256>>>(vi, ci);

    kV<<<dim3(NV, 2), 128>>>((const float4*)chn, (const float4*)mc2v,
                             (const float4*)mv2c, Wi, We, gm, (float4*)outV2C);
    kH<<<dim3(NC, 2), 128>>>((const float4*)outV2C, (const float4*)mc2v,
                             vi, We, gm, (float4*)outC2V);
    kM<<<NV, 256>>>((const float4*)chn, Wi, (float4*)outM);
}

// round 3
// speedup vs baseline: 2.1669x; 1.2919x over previous
#include <cuda_runtime.h>

// ---------------- problem constants ----------------
#define NV 16384
#define NC 8192
#define NE 65536
#define BB 1024
#define B4 256            // BB/4 float4 per row
#define CLIPV 15.0f
#define EPSF 1e-6f
#define ABS_MIN 6.1180464e-07f   // -log(tanh(15/2))

#define DC_SMEM 8         // smem-cached edges per check block (16 KB)

// ---------------- scratch (static device globals) ----------------
__device__ int g_cntV[NV];
__device__ int g_cntC[NC];
__device__ int g_rowV[NV + 1];
__device__ int g_rowC[NC + 1];
__device__ int g_curV[NV];
__device__ int g_curC[NC];
__device__ int g_edgeV[NE];
__device__ int g_edgeC[NE];

// log(tanh(x/2)), x in [ABS_MIN, 15]
__device__ __forceinline__ float logtanh_half(float x) {
    if (x > 0.5f) {
        float u = __expf(-x);
        return __logf(__fdividef(1.0f - u, 1.0f + u));
    } else {
        // log(x/2) + log(1 - x^2/12 + ...) ~= log(x/2) - x^2/12
        return __logf(0.5f * x) - 0.0833333333f * x * x;
    }
}

__device__ __forceinline__ void red_add_v4(float* p, float4 v) {
    asm volatile("red.global.add.v4.f32 [%0], {%1, %2, %3, %4};"
                 :: "l"(p), "f"(v.x), "f"(v.y), "f"(v.z), "f"(v.w) : "memory");
}

// ---------------- CSR build ----------------
__global__ void __launch_bounds__(256) kCount(const int* __restrict__ vi,
                                              const int* __restrict__ ci)
{
    int e = blockIdx.x * 256 + threadIdx.x;
    if (e < NE) {
        atomicAdd(&g_cntV[__ldg(vi + e)], 1);
        atomicAdd(&g_cntC[__ldg(ci + e)], 1);
    }
}

__global__ void __launch_bounds__(1024) kScan()
{
    const bool isV = (blockIdx.x == 0);
    const int N = isV ? NV : NC;
    int* cnt = isV ? g_cntV : g_cntC;
    int* row = isV ? g_rowV : g_rowC;
    int* cur = isV ? g_curV : g_curC;
    const int CH = N / 1024;
    int t = threadIdx.x;
    int base = t * CH;
    int local[16];
    int s = 0;
    for (int i = 0; i < CH; i++) { local[i] = s; s += cnt[base + i]; }
    __shared__ int sm[1024];
    sm[t] = s;
    __syncthreads();
    for (int d = 1; d < 1024; d <<= 1) {
        int x = (t >= d) ? sm[t - d] : 0;
        __syncthreads();
        sm[t] += x;
        __syncthreads();
    }
    int excl = (t == 0) ? 0 : sm[t - 1];
    for (int i = 0; i < CH; i++) {
        row[base + i] = excl + local[i];
        cur[base + i] = excl + local[i];
    }
    if (t == 1023) row[N] = sm[1023];
}

__global__ void __launch_bounds__(256) kFill(const int* __restrict__ vi,
                                             const int* __restrict__ ci)
{
    int e = blockIdx.x * 256 + threadIdx.x;
    if (e < NE) {
        int p = atomicAdd(&g_curV[__ldg(vi + e)], 1);
        g_edgeV[p] = e;
        int q = atomicAdd(&g_curC[__ldg(ci + e)], 1);
        g_edgeC[q] = e;
    }
}

// ---------------- init: out = Wi * chn ----------------
__global__ void __launch_bounds__(256) kInit(
    const float4* __restrict__ chn, const float* __restrict__ Wi_p,
    float4* __restrict__ outM)
{
    int n = blockIdx.x;
    int t = threadIdx.x;
    float Wi = __ldg(Wi_p);
    float4 ch = __ldg(chn + (size_t)n * B4 + t);
    outM[(size_t)n * B4 + t] =
        make_float4(Wi * ch.x, Wi * ch.y, Wi * ch.z, Wi * ch.w);
}

// ---------------- V step: variable-centric, no smem ----------------
__global__ void __launch_bounds__(128) kV(
    const float4* __restrict__ chn, const float4* __restrict__ mc2v,
    const float4* __restrict__ mv2c,
    const float* __restrict__ Wi_p, const float* __restrict__ We_p,
    const float* __restrict__ gm_p,
    float4* __restrict__ outV2C)
{
    int v = blockIdx.x;
    int col = blockIdx.y * 128 + threadIdx.x;   // float4 column
    int s = __ldg(&g_rowV[v]), e1 = __ldg(&g_rowV[v + 1]);
    int deg = e1 - s;
    if (deg == 0) return;

    float Wi = __ldg(Wi_p), We = __ldg(We_p), g = __ldg(gm_p);
    float omg = 1.0f - g;
    float4 ch = __ldg(chn + (size_t)v * B4 + col);

    float sx = 0.f, sy = 0.f, sz = 0.f, sw = 0.f;
    #pragma unroll 4
    for (int j = 0; j < deg; j++) {
        int e = __ldg(&g_edgeV[s + j]);
        float4 m = __ldg(mc2v + (size_t)e * B4 + col);
        sx += m.x; sy += m.y; sz += m.z; sw += m.w;
    }

    float ellx = Wi * ch.x, elly = Wi * ch.y, ellz = Wi * ch.z, ellw = Wi * ch.w;

    #pragma unroll 2
    for (int j = 0; j < deg; j++) {
        int e = __ldg(&g_edgeV[s + j]);
        float4 m  = __ldg(mc2v + (size_t)e * B4 + col);   // L1 hit (re-read)
        float4 mv = __ldg(mv2c + (size_t)e * B4 + col);
        float4 o;
        o.x = omg * mv.x + g * (ellx + We * (sx - m.x));
        o.y = omg * mv.y + g * (elly + We * (sy - m.y));
        o.z = omg * mv.z + g * (ellz + We * (sz - m.z));
        o.w = omg * mv.w + g * (ellw + We * (sw - m.w));
        outV2C[(size_t)e * B4 + col] = o;
    }
}

// ---------------- H step: check-centric, small smem cache ----------------
__global__ void __launch_bounds__(128) kH(
    const float4* __restrict__ v2cNew, const float4* __restrict__ mc2v,
    const int* __restrict__ vi,
    const float* __restrict__ We_p, const float* __restrict__ gm_p,
    float4* __restrict__ outC2V, float* __restrict__ outM)
{
    int c = blockIdx.x;
    int col = blockIdx.y * 128 + threadIdx.x;
    int s = __ldg(&g_rowC[c]), e1 = __ldg(&g_rowC[c + 1]);
    int deg = e1 - s;
    if (deg == 0) return;

    __shared__ float4 senc[DC_SMEM][128];   // 16 KB

    float We = __ldg(We_p), g = __ldg(gm_p);
    float omg = 1.0f - g;

    float Slt[4] = {0.f, 0.f, 0.f, 0.f};
    int   Sng[4] = {0, 0, 0, 0};

    for (int j = 0; j < deg; j++) {
        int e = __ldg(&g_edgeC[s + j]);
        float4 l4 = __ldg(v2cNew + (size_t)e * B4 + col);
        float lam[4] = {l4.x, l4.y, l4.z, l4.w};
        float enc[4];
        #pragma unroll
        for (int i = 0; i < 4; i++) {
            float lm = fminf(fmaxf(lam[i], -CLIPV), CLIPV);
            int ng = (lm < 0.f) ? 1 : 0;
            float al = fminf(fmaxf(fabsf(lm), ABS_MIN), CLIPV);
            float lt = logtanh_half(al);           // lt < 0 always
            Slt[i] += lt;
            Sng[i] += ng;
            enc[i] = ng ? -lt : lt;                // sign bit encodes ng
        }
        if (j < DC_SMEM)
            senc[j][threadIdx.x] = make_float4(enc[0], enc[1], enc[2], enc[3]);
    }

    for (int j = 0; j < deg; j++) {
        int e = __ldg(&g_edgeC[s + j]);
        int v = __ldg(vi + e);
        float lt[4]; int ng[4];
        if (j < DC_SMEM) {
            float4 e4 = senc[j][threadIdx.x];
            float enc[4] = {e4.x, e4.y, e4.z, e4.w};
            #pragma unroll
            for (int i = 0; i < 4; i++) {
                ng[i] = (enc[i] > 0.f) ? 1 : 0;
                lt[i] = -fabsf(enc[i]);
            }
        } else {
            float4 l4 = __ldg(v2cNew + (size_t)e * B4 + col);  // L1/L2 hit
            float lam[4] = {l4.x, l4.y, l4.z, l4.w};
            #pragma unroll
            for (int i = 0; i < 4; i++) {
                float lm = fminf(fmaxf(lam[i], -CLIPV), CLIPV);
                ng[i] = (lm < 0.f) ? 1 : 0;
                float al = fminf(fmaxf(fabsf(lm), ABS_MIN), CLIPV);
                lt[i] = logtanh_half(al);
            }
        }

        float4 mc = __ldg(mc2v + (size_t)e * B4 + col);
        float mcs[4] = {mc.x, mc.y, mc.z, mc.w};
        float os[4];
        #pragma unroll
        for (int i = 0; i < 4; i++) {
            float amp = fminf(Slt[i] - lt[i], 0.0f);
            int cnt = Sng[i] - ng[i];
            float sgn = (cnt & 1) ? -1.0f : 1.0f;
            float y = __expf(amp) * (1.0f - EPSF);
            float h = sgn * __logf(__fdividef(1.0f + y, 1.0f - y));
            os[i] = omg * mcs[i] + g * h;
        }
        float4 o = make_float4(os[0], os[1], os[2], os[3]);
        outC2V[(size_t)e * B4 + col] = o;

        float* dst = outM + (size_t)v * BB + col * 4;
        red_add_v4(dst, make_float4(We * o.x, We * o.y, We * o.z, We * o.w));
    }
}

// ---------------- launch ----------------
extern "C" void kernel_launch(void* const* d_in, const int* in_sizes, int n_in,
                              void* d_out, int out_size)
{
    (void)in_sizes; (void)n_in; (void)out_size;

    const float* chn  = (const float*)d_in[0];
    const float* mc2v = (const float*)d_in[1];
    const float* mv2c = (const float*)d_in[2];
    const float* Wi   = (const float*)d_in[3];
    const float* We   = (const float*)d_in[4];
    const float* gm   = (const float*)d_in[5];
    const int*   vi   = (const int*)d_in[6];
    const int*   ci   = (const int*)d_in[7];

    // outputs: (msg_C2V, msg_V2C, output)
    float* outC2V = (float*)d_out;
    float* outV2C = outC2V + (size_t)NE * BB;
    float* outM   = outV2C + (size_t)NE * BB;

    void *pcv, *pcc;
    cudaGetSymbolAddress(&pcv, g_cntV);
    cudaGetSymbolAddress(&pcc, g_cntC);
    cudaMemsetAsync(pcv, 0, sizeof(int) * NV, 0);
    cudaMemsetAsync(pcc, 0, sizeof(int) * NC, 0);

    kCount<<<NE / 256, 256>>>(vi, ci);
    kScan<<<2, 1024>>>();
    kFill<<<NE / 256, 256>>>(vi, ci);

    kInit<<<NV, 256>>>((const float4*)chn, Wi, (float4*)outM);

    kV<<<dim3(NV, 2), 128>>>((const float4*)chn, (const float4*)mc2v,
                             (const float4*)mv2c, Wi, We, gm, (float4*)outV2C);
    kH<<<dim3(NC, 2), 128>>>((const float4*)outV2C, (const float4*)mc2v,
                             vi, We, gm, (float4*)outC2V, outM);
}

// round 4
// speedup vs baseline: 2.1730x; 1.0028x over previous
#include <cuda_runtime.h>

// ---------------- problem constants ----------------
#define NV 16384
#define NC 8192
#define NE 65536
#define BB 1024
#define B4 256            // BB/4 float4 per row
#define CLIPV 15.0f
#define EPSF 1e-6f
#define ABS_MIN 6.1180464e-07f   // -log(tanh(15/2))

#define DC_SMEM 12        // smem-cached edges per check block (24 KB)
#define DV_REG 4          // reg-cached edges per variable

// ---------------- scratch (static device globals) ----------------
__device__ int g_cntV[NV];
__device__ int g_cntC[NC];
__device__ int g_rowV[NV + 1];
__device__ int g_rowC[NC + 1];
__device__ int g_curV[NV];
__device__ int g_curC[NC];
__device__ int g_edgeV[NE];
__device__ int g_edgeC[NE];

// tanh(x/2), x in [ABS_MIN, 15]; accurate both for tiny and large x
__device__ __forceinline__ float tanh_half(float x) {
    if (x > 0.5f) {
        float u = __expf(-x);                       // u <= 0.607, no cancellation
        return __fdividef(1.0f - u, 1.0f + u);
    } else {
        float z = 0.5f * x;                          // z <= 0.25
        float z2 = z * z;
        return z * (1.0f + z2 * (-0.33333333f + z2 * 0.13333333f));
    }
}

__device__ __forceinline__ void red_add_v4(float* p, float4 v) {
    asm volatile("red.global.add.v4.f32 [%0], {%1, %2, %3, %4};"
                 :: "l"(p), "f"(v.x), "f"(v.y), "f"(v.z), "f"(v.w) : "memory");
}

// ---------------- CSR build ----------------
__global__ void __launch_bounds__(256) kCount(const int* __restrict__ vi,
                                              const int* __restrict__ ci)
{
    int e = blockIdx.x * 256 + threadIdx.x;
    if (e < NE) {
        atomicAdd(&g_cntV[__ldg(vi + e)], 1);
        atomicAdd(&g_cntC[__ldg(ci + e)], 1);
    }
}

__global__ void __launch_bounds__(1024) kScan()
{
    const bool isV = (blockIdx.x == 0);
    const int N = isV ? NV : NC;
    int* cnt = isV ? g_cntV : g_cntC;
    int* row = isV ? g_rowV : g_rowC;
    int* cur = isV ? g_curV : g_curC;
    const int CH = N / 1024;
    int t = threadIdx.x;
    int base = t * CH;
    int local[16];
    int s = 0;
    for (int i = 0; i < CH; i++) { local[i] = s; s += cnt[base + i]; }
    __shared__ int sm[1024];
    sm[t] = s;
    __syncthreads();
    for (int d = 1; d < 1024; d <<= 1) {
        int x = (t >= d) ? sm[t - d] : 0;
        __syncthreads();
        sm[t] += x;
        __syncthreads();
    }
    int excl = (t == 0) ? 0 : sm[t - 1];
    for (int i = 0; i < CH; i++) {
        row[base + i] = excl + local[i];
        cur[base + i] = excl + local[i];
    }
    if (t == 1023) row[N] = sm[1023];
}

__global__ void __launch_bounds__(256) kFill(const int* __restrict__ vi,
                                             const int* __restrict__ ci)
{
    int e = blockIdx.x * 256 + threadIdx.x;
    if (e < NE) {
        int p = atomicAdd(&g_curV[__ldg(vi + e)], 1);
        g_edgeV[p] = e;
        int q = atomicAdd(&g_curC[__ldg(ci + e)], 1);
        g_edgeC[q] = e;
    }
}

// ---------------- V step (also initializes outM = Wi*chn) ----------------
__global__ void __launch_bounds__(128) kV(
    const float4* __restrict__ chn, const float4* __restrict__ mc2v,
    const float4* __restrict__ mv2c,
    const float* __restrict__ Wi_p, const float* __restrict__ We_p,
    const float* __restrict__ gm_p,
    float4* __restrict__ outV2C, float4* __restrict__ outM)
{
    int v = blockIdx.x;
    int col = blockIdx.y * 128 + threadIdx.x;   // float4 column
    int s = __ldg(&g_rowV[v]), e1 = __ldg(&g_rowV[v + 1]);
    int deg = e1 - s;

    float Wi = __ldg(Wi_p), We = __ldg(We_p), g = __ldg(gm_p);
    float omg = 1.0f - g;
    float4 ch = __ldcs(chn + (size_t)v * B4 + col);

    // init marginal output (fused kInit)
    outM[(size_t)v * B4 + col] =
        make_float4(Wi * ch.x, Wi * ch.y, Wi * ch.z, Wi * ch.w);
    if (deg == 0) return;

    float4 mreg[DV_REG];
    float sx = 0.f, sy = 0.f, sz = 0.f, sw = 0.f;
    #pragma unroll 4
    for (int j = 0; j < deg; j++) {
        int e = __ldg(&g_edgeV[s + j]);
        float4 m = __ldg(mc2v + (size_t)e * B4 + col);
        if (j < DV_REG) mreg[j] = m;
        sx += m.x; sy += m.y; sz += m.z; sw += m.w;
    }

    float ellx = Wi * ch.x, elly = Wi * ch.y, ellz = Wi * ch.z, ellw = Wi * ch.w;

    #pragma unroll 4
    for (int j = 0; j < deg; j++) {
        int e = __ldg(&g_edgeV[s + j]);
        float4 m = (j < DV_REG) ? mreg[j]
                                : __ldg(mc2v + (size_t)e * B4 + col); // L1 hit
        float4 mv = __ldcs(mv2c + (size_t)e * B4 + col);
        float4 o;
        o.x = omg * mv.x + g * (ellx + We * (sx - m.x));
        o.y = omg * mv.y + g * (elly + We * (sy - m.y));
        o.z = omg * mv.z + g * (ellz + We * (sz - m.z));
        o.w = omg * mv.w + g * (ellw + We * (sw - m.w));
        outV2C[(size_t)e * B4 + col] = o;
    }
}

// ---------------- H step: tanh-domain product formulation ----------------
__global__ void __launch_bounds__(128) kH(
    const float4* __restrict__ v2cNew, const float4* __restrict__ mc2v,
    const int* __restrict__ vi,
    const float* __restrict__ We_p, const float* __restrict__ gm_p,
    float4* __restrict__ outC2V, float* __restrict__ outM)
{
    int c = blockIdx.x;
    int col = blockIdx.y * 128 + threadIdx.x;
    int s = __ldg(&g_rowC[c]), e1 = __ldg(&g_rowC[c + 1]);
    int deg = e1 - s;
    if (deg == 0) return;

    __shared__ float4 senc[DC_SMEM][128];   // 24 KB: t_e with sign bit = neg flag

    float We = __ldg(We_p), g = __ldg(gm_p);
    float omg = 1.0f - g;

    float P[4] = {1.f, 1.f, 1.f, 1.f};
    int   Sng[4] = {0, 0, 0, 0};

    #pragma unroll 2
    for (int j = 0; j < deg; j++) {
        int e = __ldg(&g_edgeC[s + j]);
        float4 l4 = __ldg(v2cNew + (size_t)e * B4 + col);
        float lam[4] = {l4.x, l4.y, l4.z, l4.w};
        float enc[4];
        #pragma unroll
        for (int i = 0; i < 4; i++) {
            float lm = fminf(fmaxf(lam[i], -CLIPV), CLIPV);
            int ng = (lm < 0.f) ? 1 : 0;
            float al = fminf(fmaxf(fabsf(lm), ABS_MIN), CLIPV);
            float t = tanh_half(al);               // in (0,1)
            P[i] *= t;
            Sng[i] += ng;
            enc[i] = ng ? -t : t;
        }
        if (j < DC_SMEM)
            senc[j][threadIdx.x] = make_float4(enc[0], enc[1], enc[2], enc[3]);
    }

    #pragma unroll 2
    for (int j = 0; j < deg; j++) {
        int e = __ldg(&g_edgeC[s + j]);
        int v = __ldg(vi + e);
        float enc[4];
        if (j < DC_SMEM) {
            float4 e4 = senc[j][threadIdx.x];
            enc[0] = e4.x; enc[1] = e4.y; enc[2] = e4.z; enc[3] = e4.w;
        } else {
            float4 l4 = __ldg(v2cNew + (size_t)e * B4 + col);  // L1 hit
            float lam[4] = {l4.x, l4.y, l4.z, l4.w};
            #pragma unroll
            for (int i = 0; i < 4; i++) {
                float lm = fminf(fmaxf(lam[i], -CLIPV), CLIPV);
                int ng = (lm < 0.f) ? 1 : 0;
                float al = fminf(fmaxf(fabsf(lm), ABS_MIN), CLIPV);
                float t = tanh_half(al);
                enc[i] = ng ? -t : t;
            }
        }

        float4 mc = __ldcs(mc2v + (size_t)e * B4 + col);
        float mcs[4] = {mc.x, mc.y, mc.z, mc.w};
        float os[4];
        #pragma unroll
        for (int i = 0; i < 4; i++) {
            int ng = (enc[i] < 0.f) ? 1 : 0;
            float t = fabsf(enc[i]);
            float y = fminf(__fdividef(P[i], t), 1.0f) * (1.0f - EPSF);
            int cnt = Sng[i] - ng;
            float sgn = (cnt & 1) ? -1.0f : 1.0f;
            float h = sgn * __logf(__fdividef(1.0f + y, 1.0f - y)); // 2*atanh(y)
            os[i] = omg * mcs[i] + g * h;
        }
        float4 o = make_float4(os[0], os[1], os[2], os[3]);
        __stcs(outC2V + (size_t)e * B4 + col, o);

        float* dst = outM + (size_t)v * BB + col * 4;
        red_add_v4(dst, make_float4(We * o.x, We * o.y, We * o.z, We * o.w));
    }
}

// ---------------- launch ----------------
extern "C" void kernel_launch(void* const* d_in, const int* in_sizes, int n_in,
                              void* d_out, int out_size)
{
    (void)in_sizes; (void)n_in; (void)out_size;

    const float* chn  = (const float*)d_in[0];
    const float* mc2v = (const float*)d_in[1];
    const float* mv2c = (const float*)d_in[2];
    const float* Wi   = (const float*)d_in[3];
    const float* We   = (const float*)d_in[4];
    const float* gm   = (const float*)d_in[5];
    const int*   vi   = (const int*)d_in[6];
    const int*   ci   = (const int*)d_in[7];

    // outputs: (msg_C2V, msg_V2C, output)
    float* outC2V = (float*)d_out;
    float* outV2C = outC2V + (size_t)NE * BB;
    float* outM   = outV2C + (size_t)NE * BB;

    void *pcv, *pcc;
    cudaGetSymbolAddress(&pcv, g_cntV);
    cudaGetSymbolAddress(&pcc, g_cntC);
    cudaMemsetAsync(pcv, 0, sizeof(int) * NV, 0);
    cudaMemsetAsync(pcc, 0, sizeof(int) * NC, 0);

    kCount<<<NE / 256, 256>>>(vi, ci);
    kScan<<<2, 1024>>>();
    kFill<<<NE / 256, 256>>>(vi, ci);

    kV<<<dim3(NV, 2), 128>>>((const float4*)chn, (const float4*)mc2v,
                             (const float4*)mv2c, Wi, We, gm,
                             (float4*)outV2C, (float4*)outM);
    kH<<<dim3(NC, 2), 128>>>((const float4*)outV2C, (const float4*)mc2v,
                             vi, We, gm, (float4*)outC2V, outM);
}